// round 8
// baseline (speedup 1.0000x reference)
#include <cuda_runtime.h>
#include <cuda_bf16.h>

// LightGCN 3-layer propagation. CSR (dst-sorted) with packed {src,w} edges,
// atomic-free reduction (R4 prop structure — proven optimum).
// histrank also concatenates uw||iw into g_emb so all props gather branch-free.

#define NUM_USERS 100000
#define NUM_ITEMS 50000
#define NN        150000
#define DIM       64
#define EDGES     1250000

#define NQ  (NN * 16)          // float4 count of one embedding buffer
#define UQ  (NUM_USERS * 16)

#define SCAN_B 256
#define NBLK   ((NN + SCAN_B - 1) / SCAN_B)   // 586
#define OFFSZ  (NBLK * SCAN_B)

// Device-global scratch: emb/A/B = 115MB, edges 10MB, rank 5MB.
__device__ float g_emb [NN * DIM];  // uw || iw
__device__ float g_bufA[NN * DIM];
__device__ float g_bufB[NN * DIM];
__device__ int   g_cnt [NN];        // in-degree (zeroed by scan1 after use)
__device__ float g_rs  [NN];        // rs[x] = deg>0 ? rsqrt(deg) : 0
__device__ int   g_rank[EDGES];     // per-edge arrival rank within its dst
__device__ int   g_off [OFFSZ + 1]; // block-LOCAL exclusive prefix of cnt
__device__ int   g_bsum[NBLK];      // exclusive block sums
__device__ int2  g_edge[EDGES];     // {src, __float_as_int(w)} sorted by dst

// ---------------------------------------------------------------------------
// Per-warp dtype detection: all warps sample the SAME first 8 int64 slots.
// ---------------------------------------------------------------------------
__device__ __forceinline__ bool detect_is32(const void* edge) {
    int lid = threadIdx.x & 31;
    bool bad = false;
    if (lid < 8) {
        long long v = ((const long long*)edge)[lid];
        bad = (v < 0 || v >= (long long)NN);
    }
    return __ballot_sync(0xffffffffu, bad) != 0;
}

// ---------------------------------------------------------------------------
// histogram + per-edge rank; also concatenates uw||iw -> g_emb (grid-stride).
// ---------------------------------------------------------------------------
__global__ void histrank_kernel(const void* edge,
                                const float* __restrict__ uw,
                                const float* __restrict__ iw) {
    int t = blockIdx.x * blockDim.x + threadIdx.x;
    int stride = gridDim.x * blockDim.x;

    // emb concat: 2.4M float4 over ~1.25M threads (2 iters each)
    float4* e4 = (float4*)g_emb;
    for (int i = t; i < NQ; i += stride)
        e4[i] = (i < UQ) ? ((const float4*)uw)[i]
                         : ((const float4*)iw)[i - UQ];

    if (t >= EDGES) return;
    bool is32 = detect_is32(edge);
    int d;
    if (is32) d = ((const int*)edge)[EDGES + t];
    else      d = (int)((const long long*)edge)[EDGES + t];
    g_rank[t] = atomicAdd(&g_cnt[d], 1);
}

// ---------------------------------------------------------------------------
// two-phase shuffle scan; scan1 also emits rs[] and zeroes cnt (last reader).
// ---------------------------------------------------------------------------
__device__ __forceinline__ int warp_incl_scan(int v, int lid) {
    #pragma unroll
    for (int o = 1; o < 32; o <<= 1) {
        int t = __shfl_up_sync(0xffffffffu, v, o);
        if (lid >= o) v += t;
    }
    return v;
}

__global__ void scan1_kernel() {
    __shared__ int wsum[8];
    int i = blockIdx.x * SCAN_B + threadIdx.x;
    int v = (i < NN) ? g_cnt[i] : 0;
    if (i < NN) {
        g_rs[i]  = (v > 0) ? rsqrtf((float)v) : 0.f;
        g_cnt[i] = 0;                                  // reset for next replay
    }
    int wid = threadIdx.x >> 5, lid = threadIdx.x & 31;
    int incl = warp_incl_scan(v, lid);
    if (lid == 31) wsum[wid] = incl;
    __syncthreads();
    if (wid == 0) {
        int s = (lid < 8) ? wsum[lid] : 0;
        #pragma unroll
        for (int o = 1; o < 8; o <<= 1) {
            int t = __shfl_up_sync(0xffffffffu, s, o);
            if (lid >= o) s += t;
        }
        if (lid < 8) wsum[lid] = s;
    }
    __syncthreads();
    int base = (wid > 0) ? wsum[wid - 1] : 0;
    g_off[i] = base + incl - v;                        // block-local exclusive
    if (threadIdx.x == SCAN_B - 1) g_bsum[blockIdx.x] = base + incl;
    if (i == 0) g_off[OFFSZ] = 0;
}

__global__ void scan2_kernel() {   // 1 block, NBLK=586 elements, 640 threads
    __shared__ int wsum[20];
    int i = threadIdx.x;
    int lid = i & 31, wid = i >> 5;
    int v = (i < NBLK) ? g_bsum[i] : 0;
    int incl = warp_incl_scan(v, lid);
    if (lid == 31) wsum[wid] = incl;
    __syncthreads();
    if (wid == 0) {
        int s = (lid < 20) ? wsum[lid] : 0;
        #pragma unroll
        for (int o = 1; o < 32; o <<= 1) {
            int t = __shfl_up_sync(0xffffffffu, s, o);
            if (lid >= o) s += t;
        }
        if (lid < 20) wsum[lid] = s;
    }
    __syncthreads();
    int base = (wid > 0) ? wsum[wid - 1] : 0;
    if (i < NBLK) g_bsum[i] = base + incl - v;         // exclusive block prefix
}

// ---------------------------------------------------------------------------
// CSR fill: pos = off_abs(d) + rank[e]; w = rs[s] * rsqrt(deg_d) with
// deg_d = off_abs(d+1) - off_abs(d) (adjacent loads, no random cnt read).
// ---------------------------------------------------------------------------
__global__ void fill_kernel(const void* edge) {
    int e = blockIdx.x * blockDim.x + threadIdx.x;
    if (e >= EDGES) return;
    bool is32 = detect_is32(edge);
    int s, d;
    if (is32) {
        const int* ei = (const int*)edge;
        s = ei[e];
        d = ei[EDGES + e];
    } else {
        const long long* ei = (const long long*)edge;
        s = (int)ei[e];
        d = (int)ei[EDGES + e];
    }
    int off_d  = g_off[d]     + g_bsum[d >> 8];
    int off_d1 = g_off[d + 1] + g_bsum[(d + 1) >> 8];
    float deg_d = (float)(off_d1 - off_d);             // > 0 here by construction
    float w = g_rs[s] * rsqrtf(deg_d);
    int pos = off_d + g_rank[e];
    g_edge[pos] = make_int2(s, __float_as_int(w));
}

// ---------------------------------------------------------------------------
// Propagate (R4 structure). 16 lanes per node; lane c owns float4 #c.
// MODE 0: nxt[n] = sum w*cur[src].
// MODE 1: final: out = (emb + c1 + cur_row + r)/4, duplicated.
// ---------------------------------------------------------------------------
template<int MODE>
__global__ void __launch_bounds__(256)
prop_kernel(const float* __restrict__ cur,
            const float* __restrict__ c1,
            float* __restrict__ nxt,
            float* __restrict__ out) {
    int t = blockIdx.x * blockDim.x + threadIdx.x;
    int n = t >> 4;
    int c = t & 15;
    if (n >= NN) return;
    int j   = g_off[n]     + g_bsum[n >> 8];
    int end = g_off[n + 1] + g_bsum[(n + 1) >> 8];
    float4 r = make_float4(0.f, 0.f, 0.f, 0.f);

    const int2* __restrict__ ge = g_edge;
    const float4* __restrict__ c4 = (const float4*)cur;
    for (; j + 4 <= end; j += 4) {
        int2 e0 = ge[j];
        int2 e1 = ge[j + 1];
        int2 e2 = ge[j + 2];
        int2 e3 = ge[j + 3];
        float4 v0 = c4[e0.x * 16 + c];
        float4 v1 = c4[e1.x * 16 + c];
        float4 v2 = c4[e2.x * 16 + c];
        float4 v3 = c4[e3.x * 16 + c];
        float w0 = __int_as_float(e0.y), w1 = __int_as_float(e1.y);
        float w2 = __int_as_float(e2.y), w3 = __int_as_float(e3.y);
        r.x += v0.x * w0 + v1.x * w1 + v2.x * w2 + v3.x * w3;
        r.y += v0.y * w0 + v1.y * w1 + v2.y * w2 + v3.y * w3;
        r.z += v0.z * w0 + v1.z * w1 + v2.z * w2 + v3.z * w3;
        r.w += v0.w * w0 + v1.w * w1 + v2.w * w2 + v3.w * w3;
    }
    #pragma unroll 1
    for (; j < end; ++j) {
        int2 e0 = ge[j];
        float w0 = __int_as_float(e0.y);
        float4 v0 = c4[e0.x * 16 + c];
        r.x += v0.x * w0; r.y += v0.y * w0; r.z += v0.z * w0; r.w += v0.w * w0;
    }

    int idx = n * 16 + c;
    if (MODE == 1) {
        float4 e = ((const float4*)g_emb)[idx];
        float4 a = ((const float4*)c1)[idx];   // layer-1 result
        float4 b = c4[idx];                    // layer-2 result
        float4 o;
        o.x = (e.x + a.x + b.x + r.x) * 0.25f;
        o.y = (e.y + a.y + b.y + r.y) * 0.25f;
        o.z = (e.z + a.z + b.z + r.z) * 0.25f;
        o.w = (e.w + a.w + b.w + r.w) * 0.25f;
        float4* op = (float4*)out;
        op[idx]      = o;
        op[NQ + idx] = o;
    } else {
        ((float4*)nxt)[idx] = r;
    }
}

// ---------------------------------------------------------------------------
extern "C" void kernel_launch(void* const* d_in, const int* in_sizes, int n_in,
                              void* d_out, int out_size) {
    const void*  edge = d_in[0];
    const float* uw   = (const float*)d_in[1];
    const float* iw   = (const float*)d_in[2];
    float*       out  = (float*)d_out;

    float* A = nullptr;
    float* B = nullptr;
    float* E = nullptr;
    cudaGetSymbolAddress((void**)&A, g_bufA);
    cudaGetSymbolAddress((void**)&B, g_bufB);
    cudaGetSymbolAddress((void**)&E, g_emb);

    const int T = 256;
    const int grid_e = (EDGES + T - 1) / T;
    const int grid_p = (NN * 16 + T - 1) / T;

    histrank_kernel<<<grid_e, T>>>(edge, uw, iw);   // + emb concat
    scan1_kernel<<<NBLK, SCAN_B>>>();               // + rs + cnt reset
    scan2_kernel<<<1, 640>>>();
    fill_kernel<<<grid_e, T>>>(edge);

    prop_kernel<0><<<grid_p, T>>>(E, nullptr, B, nullptr);  // layer 1: emb -> B
    prop_kernel<0><<<grid_p, T>>>(B, nullptr, A, nullptr);  // layer 2: B -> A
    prop_kernel<1><<<grid_p, T>>>(A, B, nullptr, out);      // layer 3 + finalize
}

// round 9
// speedup vs baseline: 1.2884x; 1.2884x over previous
#include <cuda_runtime.h>
#include <cuda_bf16.h>

// LightGCN 3-layer propagation. CSR (dst-sorted), atomic-free reduction.
// EXACT Round-4 structure (158.4us baseline) + one additive change:
// histrank also warm-reads uw/iw into L2 so prop<0>'s gathers hit L2.

#define NUM_USERS 100000
#define NUM_ITEMS 50000
#define NN        150000
#define DIM       64
#define EDGES     1250000

#define NQ  (NN * 16)          // float4 count of one embedding buffer
#define UQ  (NUM_USERS * 16)
#define IQ  (NUM_ITEMS * 16)

#define SCAN_B 256
#define NBLK   ((NN + SCAN_B - 1) / SCAN_B)   // 586
#define OFFSZ  (NBLK * SCAN_B)                // padded offset array size

// Device-global scratch. bufA/bufB = 77MB, edges = 10MB, rank = 5MB.
__device__ float g_bufA[NN * DIM];
__device__ float g_bufB[NN * DIM];
__device__ int   g_cnt [NN];        // in-degree
__device__ int   g_rank[EDGES];     // per-edge arrival rank within its dst
__device__ int   g_off [OFFSZ + 1]; // block-LOCAL exclusive prefix of cnt
__device__ int   g_bsum[NBLK];      // exclusive block sums
__device__ int2  g_edge[EDGES];     // {src, __float_as_int(w)} sorted by dst
__device__ int   g_is32;            // edge_index dtype flag
__device__ float g_sink;            // DCE guard for the L2 warm reads

// ---------------------------------------------------------------------------
// detect dtype (block 0) + zero g_cnt (all blocks).
// ---------------------------------------------------------------------------
__global__ void detect_zero_kernel(const void* edge) {
    int i = blockIdx.x * blockDim.x + threadIdx.x;
    if (i < NN) g_cnt[i] = 0;
    if (blockIdx.x == 0) {
        __shared__ int flag;
        if (threadIdx.x == 0) flag = 0;
        __syncthreads();
        long long v = ((const long long*)edge)[threadIdx.x * 4];
        if (v < 0 || v >= (long long)NN) atomicOr(&flag, 1);
        __syncthreads();
        if (threadIdx.x == 0) g_is32 = flag;
    }
}

__device__ __forceinline__ void load_edge(const void* edge, int e, int& s, int& d) {
    if (g_is32) {
        const int* ei = (const int*)edge;
        s = ei[e];
        d = ei[EDGES + e];
    } else {
        const long long* ei = (const long long*)edge;
        s = (int)ei[e];
        d = (int)ei[EDGES + e];
    }
}

// ---------------------------------------------------------------------------
// histogram + per-edge rank (atomicAdd return value).
// ALSO: coalesced warm-read of uw/iw (38MB) to populate L2 before prop<0>.
// The streaming loads overlap the atomic latency (issue% is low here).
// ---------------------------------------------------------------------------
__global__ void histrank_kernel(const void* edge,
                                const float* __restrict__ uw,
                                const float* __restrict__ iw) {
    int t = blockIdx.x * blockDim.x + threadIdx.x;
    int stride = gridDim.x * blockDim.x;

    // L2 warm: touch every float4 of uw/iw once; guard defeats DCE.
    float acc = 0.f;
    for (int i = t; i < UQ; i += stride) { float4 v = ((const float4*)uw)[i]; acc += v.x; }
    for (int i = t; i < IQ; i += stride) { float4 v = ((const float4*)iw)[i]; acc += v.w; }
    if (acc == 1.2345678e38f) g_sink = acc;   // never true for this data

    if (t >= EDGES) return;
    int d;
    if (g_is32) d = ((const int*)edge)[EDGES + t];
    else        d = (int)((const long long*)edge)[EDGES + t];
    g_rank[t] = atomicAdd(&g_cnt[d], 1);
}

// ---------------------------------------------------------------------------
// shuffle-based scan: block-local exclusive (scan1) + block sums (scan2)
// ---------------------------------------------------------------------------
__device__ __forceinline__ int warp_incl_scan(int v, int lid) {
    #pragma unroll
    for (int o = 1; o < 32; o <<= 1) {
        int t = __shfl_up_sync(0xffffffffu, v, o);
        if (lid >= o) v += t;
    }
    return v;
}

__global__ void scan1_kernel() {
    __shared__ int wsum[8];
    int i = blockIdx.x * SCAN_B + threadIdx.x;
    int v = (i < NN) ? g_cnt[i] : 0;
    int wid = threadIdx.x >> 5, lid = threadIdx.x & 31;
    int incl = warp_incl_scan(v, lid);
    if (lid == 31) wsum[wid] = incl;
    __syncthreads();
    if (wid == 0) {
        int s = (lid < 8) ? wsum[lid] : 0;
        #pragma unroll
        for (int o = 1; o < 8; o <<= 1) {
            int t = __shfl_up_sync(0xffffffffu, s, o);
            if (lid >= o) s += t;
        }
        if (lid < 8) wsum[lid] = s;
    }
    __syncthreads();
    int base = (wid > 0) ? wsum[wid - 1] : 0;
    g_off[i] = base + incl - v;                       // block-local exclusive
    if (threadIdx.x == SCAN_B - 1) g_bsum[blockIdx.x] = base + incl;
    if (i == 0) g_off[OFFSZ] = 0;                     // padding guard
}

__global__ void scan2_kernel() {   // 1 block, NBLK=586 elements, 640 threads
    __shared__ int wsum[20];
    int i = threadIdx.x;
    int lid = i & 31, wid = i >> 5;
    int v = (i < NBLK) ? g_bsum[i] : 0;
    int incl = warp_incl_scan(v, lid);
    if (lid == 31) wsum[wid] = incl;
    __syncthreads();
    if (wid == 0) {
        int s = (lid < 20) ? wsum[lid] : 0;
        #pragma unroll
        for (int o = 1; o < 32; o <<= 1) {
            int t = __shfl_up_sync(0xffffffffu, s, o);
            if (lid >= o) s += t;
        }
        if (lid < 20) wsum[lid] = s;
    }
    __syncthreads();
    int base = (wid > 0) ? wsum[wid - 1] : 0;
    if (i < NBLK) g_bsum[i] = base + incl - v;        // exclusive block prefix
}

// ---------------------------------------------------------------------------
// CSR fill: pos = local_off[d] + bsum[d>>8] + rank[e]. No atomics.
// w = rsqrt(deg_s*deg_d), 0-guarded.
// ---------------------------------------------------------------------------
__global__ void fill_kernel(const void* edge) {
    int e = blockIdx.x * blockDim.x + threadIdx.x;
    if (e >= EDGES) return;
    int s, d;
    load_edge(edge, e, s, d);
    float p = (float)g_cnt[s] * (float)g_cnt[d];
    float w = (p > 0.f) ? rsqrtf(p) : 0.f;
    int pos = g_off[d] + g_bsum[d >> 8] + g_rank[e];
    g_edge[pos] = make_int2(s, __float_as_int(w));
}

// ---------------------------------------------------------------------------
// Propagate. 16 lanes per node; lane c owns float4 #c of the 64-float row.
// Unroll-4 gather batches (proven optimum). Offsets = local + bsum.
// MODE 0: layer 1 (gather from uw/iw) -> nxt; also re-zeroes g_cnt.
// MODE 1: middle (gather from cur) -> nxt.
// MODE 2: final: out = (emb + c1 + cur + r)/4, duplicated.
// ---------------------------------------------------------------------------
template<int MODE>
__device__ __forceinline__ float4 gather(const float* __restrict__ cur,
                                         const float* __restrict__ uw,
                                         const float* __restrict__ iw,
                                         int s, int c) {
    if (MODE == 0) {
        const float4* base = (s < NUM_USERS)
            ? (const float4*)uw + s * 16
            : (const float4*)iw + (s - NUM_USERS) * 16;
        return base[c];
    }
    return ((const float4*)cur)[s * 16 + c];
}

template<int MODE>
__global__ void __launch_bounds__(256)
prop_kernel(const float* __restrict__ cur,
            const float* __restrict__ uw,
            const float* __restrict__ iw,
            const float* __restrict__ c1,
            float* __restrict__ nxt,
            float* __restrict__ out) {
    int t = blockIdx.x * blockDim.x + threadIdx.x;
    if (MODE == 0 && t < NN) g_cnt[t] = 0;     // reset for next replay
    int n = t >> 4;
    int c = t & 15;
    if (n >= NN) return;
    int j   = g_off[n]     + g_bsum[n >> 8];
    int end = g_off[n + 1] + g_bsum[(n + 1) >> 8];
    float4 r = make_float4(0.f, 0.f, 0.f, 0.f);

    const int2* __restrict__ ge = g_edge;
    for (; j + 4 <= end; j += 4) {
        int2 e0 = ge[j];
        int2 e1 = ge[j + 1];
        int2 e2 = ge[j + 2];
        int2 e3 = ge[j + 3];
        float4 v0 = gather<MODE>(cur, uw, iw, e0.x, c);
        float4 v1 = gather<MODE>(cur, uw, iw, e1.x, c);
        float4 v2 = gather<MODE>(cur, uw, iw, e2.x, c);
        float4 v3 = gather<MODE>(cur, uw, iw, e3.x, c);
        float w0 = __int_as_float(e0.y), w1 = __int_as_float(e1.y);
        float w2 = __int_as_float(e2.y), w3 = __int_as_float(e3.y);
        r.x += v0.x * w0 + v1.x * w1 + v2.x * w2 + v3.x * w3;
        r.y += v0.y * w0 + v1.y * w1 + v2.y * w2 + v3.y * w3;
        r.z += v0.z * w0 + v1.z * w1 + v2.z * w2 + v3.z * w3;
        r.w += v0.w * w0 + v1.w * w1 + v2.w * w2 + v3.w * w3;
    }
    #pragma unroll 1
    for (; j < end; ++j) {
        int2 e0 = ge[j];
        float w0 = __int_as_float(e0.y);
        float4 v0 = gather<MODE>(cur, uw, iw, e0.x, c);
        r.x += v0.x * w0; r.y += v0.y * w0; r.z += v0.z * w0; r.w += v0.w * w0;
    }

    int idx = n * 16 + c;
    if (MODE == 2) {
        float4 e = (n < NUM_USERS) ? ((const float4*)uw)[idx]
                                   : ((const float4*)iw)[idx - UQ];
        float4 a = ((const float4*)c1)[idx];   // layer-1 result
        float4 b = ((const float4*)cur)[idx];  // layer-2 result
        float4 o;
        o.x = (e.x + a.x + b.x + r.x) * 0.25f;
        o.y = (e.y + a.y + b.y + r.y) * 0.25f;
        o.z = (e.z + a.z + b.z + r.z) * 0.25f;
        o.w = (e.w + a.w + b.w + r.w) * 0.25f;
        float4* op = (float4*)out;
        op[idx]      = o;
        op[NQ + idx] = o;
    } else {
        ((float4*)nxt)[idx] = r;
    }
}

// ---------------------------------------------------------------------------
extern "C" void kernel_launch(void* const* d_in, const int* in_sizes, int n_in,
                              void* d_out, int out_size) {
    const void*  edge = d_in[0];
    const float* uw   = (const float*)d_in[1];
    const float* iw   = (const float*)d_in[2];
    float*       out  = (float*)d_out;

    float* A = nullptr;
    float* B = nullptr;
    cudaGetSymbolAddress((void**)&A, g_bufA);
    cudaGetSymbolAddress((void**)&B, g_bufB);

    const int T = 256;
    const int grid_e = (EDGES + T - 1) / T;
    const int grid_p = (NN * 16 + T - 1) / T;

    detect_zero_kernel<<<NBLK, SCAN_B>>>(edge);
    histrank_kernel<<<grid_e, T>>>(edge, uw, iw);   // + L2 warm of uw/iw
    scan1_kernel<<<NBLK, SCAN_B>>>();
    scan2_kernel<<<1, 640>>>();
    fill_kernel<<<grid_e, T>>>(edge);

    // layer 1: emb -> B (c1); also resets g_cnt
    prop_kernel<0><<<grid_p, T>>>(nullptr, uw, iw, nullptr, B, nullptr);
    // layer 2: B -> A (c2)
    prop_kernel<1><<<grid_p, T>>>(B, nullptr, nullptr, nullptr, A, nullptr);
    // layer 3: gather A, finalize with emb + B + A, duplicated output
    prop_kernel<2><<<grid_p, T>>>(A, uw, iw, B, nullptr, out);
}